// round 13
// baseline (speedup 1.0000x reference)
#include <cuda_runtime.h>
#include <cuda_bf16.h>

// PointMatcher: pred (N=1024,20,2) vs gt (M=2048,20,2)
// dist(i,j) = mean_p ||pred[i,p]-gt[j,p]|| ; argmin over j per i.
// Quad-split-P (pq owns points {4pq..4pq+3} + {16+pq}); pairs computed with
// packed f32x2 (2 points per instruction stream), LDS.128 pair loads.
// 1024-thread blocks, <=32 regs, 2 CTAs/SM. TMA bulk double-buffered tiles.
// Outputs concatenated in d_out (float32):
//   [0..N*40) matched gt rows | [N*40..N*41) confidence | [N*41..N*42) indices

#define BI      4
#define TJ      256
#define P       20
#define ROWF    40
#define THREADS 1024
#define NTILES  8                           // M/TJ, compile-time
#define TILEF   (TJ * ROWF)                 // 10240 floats
#define TILEB   (TILEF * 4)                 // 40960 bytes
#define SMEM_BYTES (2*TILEB + BI*8 + 2*8)

typedef unsigned long long ull;

__device__ __forceinline__ float fsqrt_approx(float x) {
    float r;
    asm("sqrt.approx.f32 %0, %1;" : "=f"(r) : "f"(x));
    return r;
}
__device__ __forceinline__ ull pack2(float a, float b) {
    ull r;
    asm("mov.b64 %0, {%1,%2};" : "=l"(r) : "f"(a), "f"(b));
    return r;
}
// packed 2-point distance pair: returns d0^2,d1^2 halves summed via caller.
// xs={x0,x1}, ys={y0,y1}, npx={-px0,-px1}, npy={-py0,-py1}
__device__ __forceinline__ void pair2_d2(ull xs, ull ys, ull npx, ull npy,
                                         float& q0, float& q1) {
    ull dx, dy, qx, q;
    asm("add.rn.f32x2 %0, %1, %2;" : "=l"(dx) : "l"(xs), "l"(npx));
    asm("add.rn.f32x2 %0, %1, %2;" : "=l"(dy) : "l"(ys), "l"(npy));
    asm("mul.rn.f32x2 %0, %1, %2;" : "=l"(qx) : "l"(dx), "l"(dx));
    asm("fma.rn.f32x2 %0, %1, %2, %3;" : "=l"(q) : "l"(dy), "l"(dy), "l"(qx));
    asm("mov.b64 {%0,%1}, %2;" : "=f"(q0), "=f"(q1) : "l"(q));
}
__device__ __forceinline__ void mbar_init(unsigned mbar, unsigned cnt) {
    asm volatile("mbarrier.init.shared.b64 [%0], %1;" :: "r"(mbar), "r"(cnt) : "memory");
}
__device__ __forceinline__ void mbar_expect_tx(unsigned mbar, unsigned bytes) {
    asm volatile("mbarrier.arrive.expect_tx.shared.b64 _, [%0], %1;"
                 :: "r"(mbar), "r"(bytes) : "memory");
}
__device__ __forceinline__ void bulk_ld(unsigned dst, const void* src,
                                        unsigned bytes, unsigned mbar) {
    asm volatile(
        "cp.async.bulk.shared::cluster.global.mbarrier::complete_tx::bytes "
        "[%0], [%1], %2, [%3];"
        :: "r"(dst), "l"(src), "r"(bytes), "r"(mbar) : "memory");
}
__device__ __forceinline__ void mbar_wait(unsigned mbar, unsigned phase) {
    asm volatile(
        "{\n\t.reg .pred P1;\n\t"
        "W_%=:\n\t"
        "mbarrier.try_wait.parity.acquire.cta.shared::cta.b64 P1, [%0], %1, 0x989680;\n\t"
        "@P1 bra D_%=;\n\t"
        "bra W_%=;\n\t"
        "D_%=:\n\t}"
        :: "r"(mbar), "r"(phase) : "memory");
}

__global__ __launch_bounds__(THREADS, 2)
void pointmatcher_kernel(const float* __restrict__ pred,
                         const float* __restrict__ gt,
                         float* __restrict__ out_mp,
                         float* __restrict__ out_conf,
                         float* __restrict__ out_idx,
                         int N, int M)
{
    extern __shared__ __align__(16) float smem[];
    float* buf0 = smem;
    float* buf1 = smem + TILEF;
    ull*   best = (ull*)(smem + 2 * TILEF);
    unsigned mbar0 = (unsigned)__cvta_generic_to_shared(best + BI);
    unsigned mbar1 = mbar0 + 8;

    const int tid = threadIdx.x;
    const int il  = tid & 3;             // pred row within block
    const int pq  = (tid >> 2) & 3;      // point quarter (partners lane^4, ^8)
    const int jl  = tid >> 4;            // 0..63 -> rows jl+{0,64,128,192}
    const int i   = blockIdx.x * BI + il;

    if (tid < BI) best[tid] = ~0ull;
    if (tid == 0) { mbar_init(mbar0, 1); mbar_init(mbar1, 1); }

    // Negated pred: pair-groups A={4pq,4pq+1}, B={4pq+2,4pq+3}, single C=16+pq
    ull npxA, npyA, npxB, npyB;
    float npxC, npyC;
    {
        const float2* p2 = (const float2*)(pred + (size_t)i * ROWF);
        float2 a0 = p2[4 * pq], a1 = p2[4 * pq + 1];
        float2 b0 = p2[4 * pq + 2], b1 = p2[4 * pq + 3];
        float2 c  = p2[16 + pq];
        npxA = pack2(-a0.x, -a1.x);  npyA = pack2(-a0.y, -a1.y);
        npxB = pack2(-b0.x, -b1.x);  npyB = pack2(-b0.y, -b1.y);
        npxC = -c.x;                 npyC = -c.y;
    }

    __syncthreads();                     // mbarrier init + best[] visible
    if (tid == 0) {                      // prefetch tile 0: ONE bulk copy
        mbar_expect_tx(mbar0, TILEB);
        bulk_ld((unsigned)__cvta_generic_to_shared(buf0), gt, TILEB, mbar0);
    }

    float minv = 3.402823466e+38f;       // min of SUM over P (mean deferred)
    int   minj = 0;

    #pragma unroll
    for (int t = 0; t < NTILES; t++) {
        unsigned mb = (t & 1) ? mbar1 : mbar0;
        mbar_wait(mb, (t >> 1) & 1);     // tile t landed
        __syncthreads();                 // all threads done with other buf

        if (tid == 0 && t + 1 < NTILES) {
            unsigned mbn = ((t + 1) & 1) ? mbar1 : mbar0;
            float* dst = ((t + 1) & 1) ? buf1 : buf0;
            mbar_expect_tx(mbn, TILEB);
            bulk_ld((unsigned)__cvta_generic_to_shared(dst),
                    gt + (size_t)(t + 1) * TILEF, TILEB, mbn);
        }

        const float* tb = (t & 1) ? buf1 : buf0;
        const float* base = tb + jl * ROWF;
        float s0 = 0.f, s1 = 0.f, s2 = 0.f, s3 = 0.f;

        #pragma unroll
        for (int r = 0; r < 4; r++) {    // rows jl + 64*r
            const float* rb = base + r * 64 * ROWF;
            float& s = (r == 0) ? s0 : (r == 1) ? s1 : (r == 2) ? s2 : s3;
            // Pair group A: points 4pq, 4pq+1 (one LDS.128)
            float4 a = *(const float4*)(rb + 8 * pq);
            // Pair group B: points 4pq+2, 4pq+3
            float4 b = *(const float4*)(rb + 8 * pq + 4);
            // Single C: point 16+pq (LDS.64)
            float2 c = *(const float2*)(rb + 32 + 2 * pq);
            float q0, q1;
            pair2_d2(pack2(a.x, a.z), pack2(a.y, a.w), npxA, npyA, q0, q1);
            s += fsqrt_approx(q0);
            s += fsqrt_approx(q1);
            pair2_d2(pack2(b.x, b.z), pack2(b.y, b.w), npxB, npyB, q0, q1);
            s += fsqrt_approx(q0);
            s += fsqrt_approx(q1);
            float dx = c.x + npxC, dy = c.y + npyC;
            s += fsqrt_approx(fmaf(dx, dx, dy * dy));
        }

        // Butterfly-combine the 4 point-quarters (same il, jl).
        s0 += __shfl_xor_sync(0xffffffffu, s0, 4);
        s0 += __shfl_xor_sync(0xffffffffu, s0, 8);
        s1 += __shfl_xor_sync(0xffffffffu, s1, 4);
        s1 += __shfl_xor_sync(0xffffffffu, s1, 8);
        s2 += __shfl_xor_sync(0xffffffffu, s2, 4);
        s2 += __shfl_xor_sync(0xffffffffu, s2, 8);
        s3 += __shfl_xor_sync(0xffffffffu, s3, 4);
        s3 += __shfl_xor_sync(0xffffffffu, s3, 8);

        int jb = t * TJ + jl;
        if (s0 < minv) { minv = s0; minj = jb;       }  // ascending j order:
        if (s1 < minv) { minv = s1; minj = jb + 64;  }  // strict '<' keeps
        if (s2 < minv) { minv = s2; minj = jb + 128; }  // first occurrence
        if (s3 < minv) { minv = s3; minj = jb + 192; }
    }

    // Block argmin: packed (dist_bits, j); min == (min dist, then min j).
    if (pq == 0) {
        ull key = ((ull)__float_as_uint(minv) << 32) | (unsigned)minj;
        atomicMin(&best[il], key);
    }
    __syncthreads();

    if (tid < BI) {
        ull b = best[tid];
        int j = (int)(unsigned)b;
        float md = __uint_as_float((unsigned)(b >> 32)) * (1.0f / (float)P);
        int row  = blockIdx.x * BI + tid;
        out_conf[row] = (md > 2.0f) ? 0.0f : expf(-md);
        out_idx[row]  = (float)j;
    }
    if (tid < BI * ROWF) {
        int ilg = tid / ROWF;
        int k   = tid - ilg * ROWF;
        int j   = (int)(unsigned)best[ilg];
        out_mp[(blockIdx.x * BI + ilg) * ROWF + k] = gt[(size_t)j * ROWF + k];
    }
}

extern "C" void kernel_launch(void* const* d_in, const int* in_sizes, int n_in,
                              void* d_out, int out_size)
{
    const float* pred = (const float*)d_in[0];
    const float* gt   = (const float*)d_in[1];
    float* out        = (float*)d_out;

    int N = in_sizes[0] / ROWF;   // 1024
    int M = in_sizes[1] / ROWF;   // 2048

    float* out_mp   = out;
    float* out_conf = out + (size_t)N * ROWF;
    float* out_idx  = out + (size_t)N * ROWF + N;

    static bool attr_set = false;  // host-side only; not in the captured graph
    if (!attr_set) {
        cudaFuncSetAttribute(pointmatcher_kernel,
                             cudaFuncAttributeMaxDynamicSharedMemorySize,
                             SMEM_BYTES);
        attr_set = true;
    }

    pointmatcher_kernel<<<N / BI, THREADS, SMEM_BYTES>>>(
        pred, gt, out_mp, out_conf, out_idx, N, M);
}